// round 16
// baseline (speedup 1.0000x reference)
#include <cuda_runtime.h>
#include <cuda_fp16.h>

#define H     4096
#define K     32
#define WO    4065
#define HP2   2048            // half2 (uint) pitch of scratch rows
#define COUT  65              // output rows per consumer chunk
#define NSEG  63              // consumer j-chunks
#define PPRE  160             // prologue producer rows
#define SEGSZ 73              // 65 producers + 8 consumers per segment
#define NCTA  (PPRE + NSEG * SEGSZ)   // 4759

__device__ unsigned g_tmp[(size_t)H * HP2];   // fp16 scratch, 33.5 MB
__device__ int g_cnt[64];                     // per-64-row completion counters

__device__ __forceinline__ int sk(int x) { return x + (x >> 4); }
__device__ __forceinline__ int hs(int i) { return i + (i >> 3); }

__device__ __forceinline__ float4 ldcs4(const float4* p) {
    float4 r;
    asm volatile("ld.global.cs.v4.f32 {%0,%1,%2,%3}, [%4];"
                 : "=f"(r.x), "=f"(r.y), "=f"(r.z), "=f"(r.w) : "l"(p));
    return r;
}
__device__ __forceinline__ void stcs(float* p, float v) {
    asm volatile("st.global.cs.f32 [%0], %1;" :: "l"(p), "f"(v));
}
__device__ __forceinline__ float2 uph2(unsigned u) {
    return __half22float2(*(const __half2*)&u);
}

__global__ void reset_flags() { if (threadIdx.x < 64) g_cnt[threadIdx.x] = 0; }

// Interleaved producer/consumer schedule. Bid order:
//   [0,160)                          : producer rows 0..159 (prologue)
//   segment s (s=0..62), 73 bids     : 65 producers (rows 160+65s .. 224+65s)
//                                      then 8 consumers (chunk j0=65s, xb 0..7)
// Consumer chunk s needs input rows <= 65s+95; rows dispatched before it:
// 160+65(s+1) = 65s+225  ->  129 rows of slack. All dependencies have lower
// bids; producers never wait  =>  deadlock-free, continuous overlap.
__global__ void __launch_bounds__(256, 4)
fused_pc(const float* __restrict__ img,
         const float* __restrict__ som,
         const float* __restrict__ var,
         float* __restrict__ out)
{
    __shared__ float d[4352];
    __shared__ float irow[32];

    const int b = blockIdx.x;
    const int t = threadIdx.x;

    int y = -1, by = -1, xb = 0;
    if (b < PPRE) {
        y = b;
    } else {
        const int u   = b - PPRE;
        const int seg = u / SEGSZ;
        const int pos = u - seg * SEGSZ;
        if (pos < 65) {
            y = PPRE + seg * 65 + pos;
            if (y >= H) return;            // tail clamp (schedule covers 4255 rows)
        } else {
            by = seg;
            xb = pos - 65;
        }
    }

    if (y >= 0) {
        // ===================== PRODUCER: one row =====================
        if (t < 32) irow[t] = img[((y & 31) << 5) + t];
        __syncthreads();

        const float4* s4 = (const float4*)(som + (size_t)y * H);
        const float4* v4 = (const float4*)(var + (size_t)y * H);
        const float4  iv = ((const float4*)irow)[t & 7];

#pragma unroll
        for (int k = 0; k < 4; k++) {
            int i4 = t + (k << 8);
            float4 s = ldcs4(s4 + i4);
            float4 v = ldcs4(v4 + i4);
            int x = i4 << 2;
            float f0 = iv.x - s.x, f1 = iv.y - s.y;
            float f2 = iv.z - s.z, f3 = iv.w - s.w;
            d[sk(x)]     = __fdividef(f0 * f0, v.x + 1e-8f);
            d[sk(x + 1)] = __fdividef(f1 * f1, v.y + 1e-8f);
            d[sk(x + 2)] = __fdividef(f2 * f2, v.z + 1e-8f);
            d[sk(x + 3)] = __fdividef(f3 * f3, v.w + 1e-8f);
        }
        __syncthreads();

        const int base = t << 4;
        const int jmax = (base < WO) ? min(16, WO - base) : 0;
        float res[16];
#pragma unroll
        for (int j = 0; j < 16; j++) res[j] = 0.f;

        if (jmax > 0) {
            float s = 0.f;
#pragma unroll
            for (int i = 0; i < K; i++) s += d[sk(base + i)];
            res[0] = s;
#pragma unroll
            for (int j = 1; j < 16; j++) {
                s += d[sk(base + j + K - 1)] - d[sk(base + j - 1)];
                if (j < jmax) res[j] = s;
            }
        }
        __syncthreads();

        unsigned* hbuf = (unsigned*)d;
#pragma unroll
        for (int p = 0; p < 8; p++) {
            __half2 h = __floats2half2_rn(res[2 * p], res[2 * p + 1]);
            hbuf[hs((t << 3) + p)] = *(unsigned*)&h;
        }
        __syncthreads();

        unsigned* grow = g_tmp + (size_t)y * HP2;
#pragma unroll
        for (int k = 0; k < 8; k++) {
            int idx = t + (k << 8);
            if (idx < 2033) grow[idx] = hbuf[hs(idx)];
        }

        __threadfence();                 // publish scratch row
        __syncthreads();
        if (t == 0) atomicAdd(&g_cnt[y >> 6], 1);
    } else {
        // ===================== CONSUMER: one 65-row x 512-col chunk ==========
        const int j0 = by * COUT;        // <= 4030
        const int n  = min(COUT, WO - j0);
        const int gF = j0 >> 6;
        const int gL = min(63, (j0 + n + 30) >> 6);

        if (t == 0) {
#pragma unroll 1
            for (int g = gF; g <= gL; g++)
                while (*(volatile int*)&g_cnt[g] < 64) __nanosleep(64);
        }
        __syncthreads();
        __threadfence();                 // acquire side

        const int c2 = (xb << 8) + t;    // xb 0..7 -> 2048 half2 cols
        if (c2 < 2033) {
            const int x0 = c2 << 1;
            const bool x1ok = (x0 + 1) < WO;
            const unsigned* col = g_tmp + c2;

            float s0 = 0.f, s1 = 0.f;
            {
                unsigned u[K];
#pragma unroll
                for (int r = 0; r < K; r++)
                    u[r] = col[(size_t)(j0 + r) * HP2];
#pragma unroll
                for (int r = 0; r < K; r++) {
                    float2 v = uph2(u[r]);
                    s0 += v.x; s1 += v.y;
                }
            }
            {
                float* o = out + (size_t)j0 * WO + x0;
                stcs(o, s0);
                if (x1ok) stcs(o + 1, s1);
            }

            for (int r = 1; r < n; r += 8) {
                const int m = min(8, n - r);
                unsigned ua[8], ub[8];
#pragma unroll
                for (int i = 0; i < 8; i++) {
                    if (i < m) {
                        ua[i] = col[(size_t)(j0 + r + i + K - 1) * HP2];
                        ub[i] = col[(size_t)(j0 + r + i - 1) * HP2];
                    }
                }
#pragma unroll
                for (int i = 0; i < 8; i++) {
                    if (i < m) {
                        float2 a  = uph2(ua[i]);
                        float2 bb = uph2(ub[i]);
                        s0 += a.x - bb.x;
                        s1 += a.y - bb.y;
                        float* o = out + (size_t)(j0 + r + i) * WO + x0;
                        stcs(o, s0);
                        if (x1ok) stcs(o + 1, s1);
                    }
                }
            }
        }
    }
}

// ---------------------------------------------------------------------------
extern "C" void kernel_launch(void* const* d_in, const int* in_sizes, int n_in,
                              void* d_out, int out_size)
{
    const float* img = (const float*)d_in[0];   // [32,32]
    const float* som = (const float*)d_in[1];   // [4096,4096]
    const float* var = (const float*)d_in[2];   // [4096,4096]
    float*       out = (float*)d_out;           // [4065,4065]

    reset_flags<<<1, 64>>>();
    fused_pc<<<NCTA, 256>>>(img, som, var, out);
}

// round 17
// speedup vs baseline: 1.2053x; 1.2053x over previous
#include <cuda_runtime.h>
#include <cuda_fp16.h>

#define H     4096
#define K     32
#define WO    4065
#define HP2   2048            // half2 (uint) pitch of scratch rows
#define COUT  129             // outputs per pass-2 chunk (1 + 4*32)

// fp16 scratch: 4096 rows x 2048 half2 = 33.5 MB
__device__ unsigned g_tmp[(size_t)H * HP2];

__device__ __forceinline__ int sk(int x) { return x + (x >> 4); }
__device__ __forceinline__ int hs(int i) { return i + (i >> 3); }

__device__ __forceinline__ float4 ldcs4(const float4* p) {
    float4 r;
    asm volatile("ld.global.cs.v4.f32 {%0,%1,%2,%3}, [%4];"
                 : "=f"(r.x), "=f"(r.y), "=f"(r.z), "=f"(r.w) : "l"(p));
    return r;
}
__device__ __forceinline__ void stcs(float* p, float v) {
    asm volatile("st.global.cs.f32 [%0], %1;" :: "l"(p), "f"(v));
}

// ---------------------------------------------------------------------------
// Pass 1 (unchanged, ~6.1 TB/s): dist + horizontal 32-wide box sum -> fp16
// ---------------------------------------------------------------------------
__global__ void __launch_bounds__(256, 8)
row_pass(const float* __restrict__ img,
         const float* __restrict__ som,
         const float* __restrict__ var)
{
    __shared__ float d[4352];
    __shared__ float irow[32];

    const int y = blockIdx.x;
    const int t = threadIdx.x;

    if (t < 32) irow[t] = img[((y & 31) << 5) + t];
    __syncthreads();

    const float4* s4 = (const float4*)(som + (size_t)y * H);
    const float4* v4 = (const float4*)(var + (size_t)y * H);
    const float4  iv = ((const float4*)irow)[t & 7];

#pragma unroll
    for (int k = 0; k < 4; k++) {
        int i4 = t + (k << 8);
        float4 s = ldcs4(s4 + i4);
        float4 v = ldcs4(v4 + i4);
        int x = i4 << 2;
        float f0 = iv.x - s.x, f1 = iv.y - s.y, f2 = iv.z - s.z, f3 = iv.w - s.w;
        d[sk(x)]     = __fdividef(f0 * f0, v.x + 1e-8f);
        d[sk(x + 1)] = __fdividef(f1 * f1, v.y + 1e-8f);
        d[sk(x + 2)] = __fdividef(f2 * f2, v.z + 1e-8f);
        d[sk(x + 3)] = __fdividef(f3 * f3, v.w + 1e-8f);
    }
    __syncthreads();

    const int base = t << 4;
    const int jmax = (base < WO) ? min(16, WO - base) : 0;
    float res[16];
#pragma unroll
    for (int j = 0; j < 16; j++) res[j] = 0.f;

    if (jmax > 0) {
        float s = 0.f;
#pragma unroll
        for (int i = 0; i < K; i++) s += d[sk(base + i)];
        res[0] = s;
#pragma unroll
        for (int j = 1; j < 16; j++) {
            s += d[sk(base + j + K - 1)] - d[sk(base + j - 1)];
            if (j < jmax) res[j] = s;
        }
    }
    __syncthreads();

    unsigned* hbuf = (unsigned*)d;
#pragma unroll
    for (int p = 0; p < 8; p++) {
        __half2 h = __floats2half2_rn(res[2 * p], res[2 * p + 1]);
        hbuf[hs((t << 3) + p)] = *(unsigned*)&h;
    }
    __syncthreads();

    unsigned* grow = g_tmp + (size_t)y * HP2;
#pragma unroll
    for (int k = 0; k < 8; k++) {
        int idx = t + (k << 8);
        if (idx < 2033) grow[idx] = hbuf[hs(idx)];
    }
}

// ---------------------------------------------------------------------------
// Pass 2: one column per thread, 32-deep fp32 register ring, 129-output
// chunks (warmup + 4 x 32-row blocks). Scratch-read redundancy 1.24x
// (was 1.48x at COUT=65). Warp = 32 consecutive cols: full-efficiency
// stores, pair-merged loads.
// ---------------------------------------------------------------------------
__global__ void __launch_bounds__(256)
col_pass(float* __restrict__ out)
{
    const int x   = blockIdx.x * 256 + threadIdx.x;      // output column
    const int par = (x & 1) ? 16 : 0;
    const unsigned* col = g_tmp + (x >> 1);
    const bool ok = x < WO;

    const int j0 = blockIdx.y * COUT;                    // 32 chunks

    unsigned u[32];
    float    pv[32];
    float    s = 0.f;

    // warmup rows j0 .. j0+31  (j0 <= 3999 -> j0+31 <= 4030 < H)
#pragma unroll
    for (int i = 0; i < 32; i++)
        u[i] = col[(size_t)(j0 + i) * HP2];
#pragma unroll
    for (int i = 0; i < 32; i++) {
        float v = __half2float(__ushort_as_half((unsigned short)(u[i] >> par)));
        pv[i] = v;
        s += v;
    }
    if (ok && j0 < WO) stcs(out + (size_t)j0 * WO + x, s);

    // 4 blocks of 32 rows; dynamic outer loop keeps code compact, inner
    // unrolled loops keep u[]/pv[] in registers.
#pragma unroll 1
    for (int blk = 0; blk < 4; blk++) {
        const int rbase = j0 + 32 + (blk << 5);
        const int jb    = j0 + 1 + (blk << 5);
#pragma unroll
        for (int i = 0; i < 32; i++) {
            int r = min(rbase + i, H - 1);               // clamped rows never output
            u[i] = col[(size_t)r * HP2];
        }
#pragma unroll
        for (int i = 0; i < 32; i++) {
            float v = __half2float(__ushort_as_half((unsigned short)(u[i] >> par)));
            s += v - pv[i];
            pv[i] = v;
            int j = jb + i;
            if (ok && j < WO) stcs(out + (size_t)j * WO + x, s);
        }
    }
}

// ---------------------------------------------------------------------------
extern "C" void kernel_launch(void* const* d_in, const int* in_sizes, int n_in,
                              void* d_out, int out_size)
{
    const float* img = (const float*)d_in[0];   // [32,32]
    const float* som = (const float*)d_in[1];   // [4096,4096]
    const float* var = (const float*)d_in[2];   // [4096,4096]
    float*       out = (float*)d_out;           // [4065,4065]

    row_pass<<<H, 256>>>(img, som, var);

    dim3 grid2(16,                              // 4096 cols / 256
               (WO + COUT - 1) / COUT);         // 32 -> 512 CTAs
    col_pass<<<grid2, 256>>>(out);
}